// round 15
// baseline (speedup 1.0000x reference)
#include <cuda_runtime.h>
#include <math.h>

// Bit-exact replication of the JAX reference on XLA:CPU (validated R9/R12/R13,
// rel_err=0.0). FP op shapes FROZEN:
//   - outside fori_loop: plain __f*_rn ops in reference association order
//   - inside fori_loop body: FMA-contracted F/Fp
//   - exp = fused-Cephes GenerateVF32Exp
// R15 perf design:
//   - 2 elements/thread (float2 I/O), chains interleaved for ILP.
//   - CRITICAL (R10/R11/R14 lesson): never step a converged chain — at the
//     fixed point F is ~0/denormal and __fdiv_rn's FCHK branches to the
//     integer slow path, dragging the warp (~2x). Joint loop exits when
//     EITHER chain closes; per-chain tail loops finish the other alone.
//   - Each chain executes exactly R13's pair semantics: pairs of frozen
//     steps, closure check (T2==T1)||(T2==Te), max 25 pairs -> bit-exact.

__device__ __forceinline__ float xla_vf32_exp(float x)
{
    x = fminf(x, 88.3762626647950f);
    x = fmaxf(x, -88.3762626647949f);

    float fx = floorf(fmaf(x, 1.44269504088896341f, 0.5f));

    float tmp = __fmul_rn(fx, 0.693359375f);
    float z   = __fmul_rn(fx, -2.12194440e-4f);
    x = __fsub_rn(x, tmp);
    x = __fsub_rn(x, z);

    float zz = __fmul_rn(x, x);

    float y = 1.9875691500e-4f;
    y = fmaf(y, x, 1.3981999507e-3f);
    y = fmaf(y, x, 8.3334519073e-3f);
    y = fmaf(y, x, 4.1665795894e-2f);
    y = fmaf(y, x, 1.6666665459e-1f);
    y = fmaf(y, x, 5.0000001201e-1f);
    y = fmaf(y, zz, x);
    y = __fadd_rn(y, 1.0f);

    int emm0 = (int)fx + 127;
    float pow2n = __int_as_float(emm0 << 23);
    return __fmul_rn(y, pow2n);
}

// One EXACT Newton step (bit-frozen op shapes — do not modify).
__device__ __forceinline__ float newton_step(float Te, float B, float C,
                                             float C2, float D)
{
    const float A_CONST = 5.4e-8f;
    const float A4      = (float)(4.0 * 5.4e-8);
    float t   = __fadd_rn(Te, 273.16f);
    float t2  = __fmul_rn(t, t);
    float t4  = __fmul_rn(t2, t2);
    float t3  = __fmul_rn(t2, t);
    float m2  = __fmul_rn(C, __fmul_rn(Te, Te));
    float F   = __fsub_rn(fmaf(B, Te, fmaf(A_CONST, t4, -m2)), D);
    float c2t = __fmul_rn(C2, Te);
    float Fp  = __fadd_rn(fmaf(A4, t3, -c2t), B);
    return __fsub_rn(Te, __fdiv_rn(F, Fp));
}

// Prologue for one element: B, C, C2, D (frozen shapes).
__device__ __forceinline__ void prologue(
    float ta, float ea, float st, float cf, float Ein,
    float elevv, float tg, float sfrv, float alb, float sw,
    float& B, float& C, float& C2, float& D)
{
    const float EV_STB  = (float)(0.9 * 5.670373e-8);
    const float C2495E6 = (float)(2495.0 * 1e6);

    float arg = __fdiv_rn(__fmul_rn(17.26939f, ta), __fadd_rn(237.3f, ta));
    float es  = __fmul_rn(6.108f, xla_vf32_exp(arg));

    float P = __fsub_rn(1013.0f, __fmul_rn(0.1055f, elevv));

    float denom  = __fsub_rn(es, ea);
    float denom1 = __fmul_rn(denom, (denom >= 0.0f) ? 1.0f : 0.0f);
    float denom2 = __fadd_rn(denom1, (denom1 == 0.0f) ? 0.01f : 0.0f);
    float Bc = __fdiv_rn(__fmul_rn(0.00061f, P), denom2);

    float tk  = __fadd_rn(ta, 273.16f);
    float tk2 = __fmul_rn(tk, tk);
    float Tk4 = __fmul_rn(tk2, tk2);

    float h1 = __fadd_rn(3.354939e-8f, __fmul_rn(2.74995e-9f, __fsqrt_rn(ea)));
    float h2 = __fsub_rn(1.0f, st);
    float h3 = __fadd_rn(1.0f, __fmul_rn(0.17f, __fmul_rn(cf, cf)));
    float Ha = __fmul_rn(__fmul_rn(__fmul_rn(h1, h2), h3), Tk4);

    float Hs = __fmul_rn(__fmul_rn(__fsub_rn(1.0f, alb), h2), sw);

    float Hv = __fmul_rn(__fmul_rn(EV_STB, sfrv), Tk4);

    float Em = __fmul_rn(1e6f, Ein);
    float b2 = __fadd_rn(2495.0f, __fmul_rn(2.36f, ta));
    float b4 = __fsub_rn(__fmul_rn(Bc, b2), 2.36f);
    B  = __fadd_rn(__fmul_rn(Em, b4), 1.65f);

    C = __fmul_rn(__fmul_rn(Em, Bc), 2.36f);

    float d3 = __fsub_rn(__fmul_rn(Bc, ta), 1.0f);
    float d4 = __fmul_rn(__fmul_rn(C2495E6, Ein), d3);
    float d5 = __fmul_rn(tg, 1.65f);
    D  = __fadd_rn(__fadd_rn(__fadd_rn(__fadd_rn(Ha, Hs), Hv), d4), d5);

    C2 = __fmul_rn(2.0f, C);
}

// Epilogue for one element: K1, K2 (frozen shapes).
__device__ __forceinline__ void epilogue(
    float Te, float t0, float B, float C, float C2, float D,
    float& K1, float& K2)
{
    const float A_CONST = 5.4e-8f;
    const float A4      = (float)(4.0 * 5.4e-8);

    float u    = __fadd_rn(t0, 273.16f);
    float u2   = __fmul_rn(u, u);
    float u4   = __fmul_rn(u2, u2);
    float t0sq = __fmul_rn(t0, t0);
    float Hi   = __fsub_rn(
                   __fadd_rn(
                     __fsub_rn(__fmul_rn(A_CONST, u4), __fmul_rn(C, t0sq)),
                     __fmul_rn(B, t0)),
                   D);

    float v  = __fadd_rn(Te, 273.16f);
    float v2 = __fmul_rn(v, v);
    float v3 = __fmul_rn(v2, v);
    K1 = __fadd_rn(
           __fsub_rn(__fmul_rn(A4, v3), __fmul_rn(C2, Te)),
           B);

    float delt = __fsub_rn(t0, Te);
    float den  = __fmul_rn(delt, delt);
    float den1 = __fadd_rn(den, (den <= 1e-10f) ? 1.0f : 0.0f);
    K2 = __fdiv_rn(__fsub_rn(__fmul_rn(K1, delt), Hi), den1);
    if (fabsf(delt) < 1e-10f) K2 = 0.0f;
}

__global__ void sntemp_kernel(
    const float* __restrict__ T_a,
    const float* __restrict__ swrad,
    const float* __restrict__ e_a,
    const float* __restrict__ E,
    const float* __restrict__ elev,
    const float* __restrict__ T_g,
    const float* __restrict__ sfr,
    const float* __restrict__ albedo,
    const float* __restrict__ shade_total,
    const float* __restrict__ cloud_fraction,
    const float* __restrict__ T_0,
    float* __restrict__ out,
    int n)
{
    int p  = blockIdx.x * blockDim.x + threadIdx.x;
    int i0 = 2 * p;
    if (i0 >= n) return;
    bool has2 = (i0 + 1) < n;

    #define LD2(ptr) (has2 ? *reinterpret_cast<const float2*>((ptr) + i0) \
                           : make_float2((ptr)[i0], (ptr)[i0]))
    float2 ta  = LD2(T_a);
    float2 ea  = LD2(e_a);
    float2 st  = LD2(shade_total);
    float2 cf  = LD2(cloud_fraction);
    float2 Ein = LD2(E);
    float2 el  = LD2(elev);
    float2 tg  = LD2(T_g);
    float2 sf  = LD2(sfr);
    float2 al  = LD2(albedo);
    float2 sw  = LD2(swrad);
    float2 t0  = LD2(T_0);
    #undef LD2

    float BA, CA, C2A, DA, BB, CB, C2B, DB;
    prologue(ta.x, ea.x, st.x, cf.x, Ein.x, el.x, tg.x, sf.x, al.x, sw.x,
             BA, CA, C2A, DA);
    prologue(ta.y, ea.y, st.y, cf.y, Ein.y, el.y, tg.y, sf.y, al.y, sw.y,
             BB, CB, C2B, DB);

    // Newton: each chain = 25 pairs max with R13 closure checks (bit-exact).
    // Joint loop interleaves both chains (ILP); exits as soon as EITHER chain
    // closes so a converged chain is NEVER stepped again (denormal-F division
    // would hit __fdiv_rn's FCHK slow path and stall the warp).
    float TeA = ta.x;
    float TeB = ta.y;
    bool  doneA = false, doneB = false;
    int   rem = 25;

    #pragma unroll 1
    while (rem > 0) {
        float a1 = newton_step(TeA, BA, CA, C2A, DA);
        float b1 = newton_step(TeB, BB, CB, C2B, DB);
        float a2 = newton_step(a1, BA, CA, C2A, DA);
        float b2 = newton_step(b1, BB, CB, C2B, DB);
        doneA = (a2 == a1) || (a2 == TeA);
        doneB = (b2 == b1) || (b2 == TeB);
        TeA = a2;
        TeB = b2;
        --rem;
        if (doneA || doneB) break;
    }

    // Tail: finish the unconverged chain alone (same pair semantics).
    if (!doneA) {
        #pragma unroll 1
        while (rem > 0) {
            float a1 = newton_step(TeA, BA, CA, C2A, DA);
            float a2 = newton_step(a1, BA, CA, C2A, DA);
            bool d = (a2 == a1) || (a2 == TeA);
            TeA = a2;
            --rem;
            if (d) break;
        }
    } else if (!doneB) {
        #pragma unroll 1
        while (rem > 0) {
            float b1 = newton_step(TeB, BB, CB, C2B, DB);
            float b2 = newton_step(b1, BB, CB, C2B, DB);
            bool d = (b2 == b1) || (b2 == TeB);
            TeB = b2;
            --rem;
            if (d) break;
        }
    }

    float K1A, K2A, K1B, K2B;
    epilogue(TeA, t0.x, BA, CA, C2A, DA, K1A, K2A);
    epilogue(TeB, t0.y, BB, CB, C2B, DB, K1B, K2B);

    if (has2) {
        *reinterpret_cast<float2*>(out + i0)         = make_float2(TeA, TeB);
        *reinterpret_cast<float2*>(out + n + i0)     = make_float2(K1A, K1B);
        *reinterpret_cast<float2*>(out + 2 * n + i0) = make_float2(K2A, K2B);
    } else {
        out[i0]         = TeA;
        out[n + i0]     = K1A;
        out[2 * n + i0] = K2A;
    }
}

extern "C" void kernel_launch(void* const* d_in, const int* in_sizes, int n_in,
                              void* d_out, int out_size) {
    // metadata order: T_a, swrad, e_a, E, elev, slope, top_width, up_inflow,
    // T_g, shade_fraction_riparian, albedo, shade_total, cloud_fraction, T_0
    const float* T_a    = (const float*)d_in[0];
    const float* swrad  = (const float*)d_in[1];
    const float* e_a    = (const float*)d_in[2];
    const float* E      = (const float*)d_in[3];
    const float* elev   = (const float*)d_in[4];
    const float* T_g    = (const float*)d_in[8];
    const float* sfr    = (const float*)d_in[9];
    const float* albedo = (const float*)d_in[10];
    const float* stot   = (const float*)d_in[11];
    const float* cf     = (const float*)d_in[12];
    const float* T_0    = (const float*)d_in[13];

    int n = in_sizes[0];
    float* out = (float*)d_out;

    int threads = 256;
    int pairs   = (n + 1) / 2;
    int blocks  = (pairs + threads - 1) / threads;
    sntemp_kernel<<<blocks, threads>>>(T_a, swrad, e_a, E, elev, T_g, sfr,
                                       albedo, stot, cf, T_0, out, n);
}

// round 16
// speedup vs baseline: 2.4190x; 2.4190x over previous
#include <cuda_runtime.h>
#include <math.h>

// Bit-exact replication of the JAX reference on XLA:CPU (validated R9/R12/R13,
// rel_err=0.0). FP op shapes FROZEN:
//   - outside fori_loop: plain __f*_rn ops in reference association order
//   - inside fori_loop body: FMA-contracted F/Fp
//   - exp = fused-Cephes GenerateVF32Exp
// R16 perf change: the Newton-loop division uses a hand-inlined
// rcp-seed + NR + Markstein correction — the EXACT fast-path sequence ptxas
// emits for div.rn.f32, minus FCHK and its BSSY/BSYNC/BRA scaffolding.
// Bit-identical for our operands: Fp in [~2,1e5] normal positive; F is a
// difference of two ~O(400) floats so F ∈ {+0} ∪ |F|>=~3e-5 (no denormals);
// F=+0 gives q=+0 in both paths. Structure otherwise identical to R13
// (1 elem/thread, 25 fully-unrolled pairs, prompt per-lane exit — R14/R15
// lessons: never step a converged chain; never batch elements per thread).

__device__ __forceinline__ float xla_vf32_exp(float x)
{
    x = fminf(x, 88.3762626647950f);
    x = fmaxf(x, -88.3762626647949f);

    float fx = floorf(fmaf(x, 1.44269504088896341f, 0.5f));

    float tmp = __fmul_rn(fx, 0.693359375f);
    float z   = __fmul_rn(fx, -2.12194440e-4f);
    x = __fsub_rn(x, tmp);
    x = __fsub_rn(x, z);

    float zz = __fmul_rn(x, x);

    float y = 1.9875691500e-4f;
    y = fmaf(y, x, 1.3981999507e-3f);
    y = fmaf(y, x, 8.3334519073e-3f);
    y = fmaf(y, x, 4.1665795894e-2f);
    y = fmaf(y, x, 1.6666665459e-1f);
    y = fmaf(y, x, 5.0000001201e-1f);
    y = fmaf(y, zz, x);
    y = __fadd_rn(y, 1.0f);

    int emm0 = (int)fx + 127;
    float pow2n = __int_as_float(emm0 << 23);
    return __fmul_rn(y, pow2n);
}

// Correctly-rounded f32 division for normal operands: identical instruction
// sequence to ptxas's div.rn.f32 fast path (MUFU.RCP seed, one NR refinement,
// Markstein quotient correction) without the FCHK special-case guard.
__device__ __forceinline__ float div_rn_fast(float a, float b)
{
    float y0;
    asm("rcp.approx.ftz.f32 %0, %1;" : "=f"(y0) : "f"(b));
    float e  = __fmaf_rn(-b, y0, 1.0f);
    float y1 = __fmaf_rn(y0, e, y0);
    float q0 = __fmul_rn(a, y1);
    float r  = __fmaf_rn(-b, q0, a);
    return __fmaf_rn(r, y1, q0);
}

// One EXACT Newton step (bit-frozen op shapes — do not modify).
__device__ __forceinline__ float newton_step(float Te, float B, float C,
                                             float C2, float D)
{
    const float A_CONST = 5.4e-8f;
    const float A4      = (float)(4.0 * 5.4e-8);
    float t   = __fadd_rn(Te, 273.16f);
    float t2  = __fmul_rn(t, t);
    float t4  = __fmul_rn(t2, t2);
    float t3  = __fmul_rn(t2, t);
    float m2  = __fmul_rn(C, __fmul_rn(Te, Te));
    float F   = __fsub_rn(fmaf(B, Te, fmaf(A_CONST, t4, -m2)), D);
    float c2t = __fmul_rn(C2, Te);
    float Fp  = __fadd_rn(fmaf(A4, t3, -c2t), B);
    return __fsub_rn(Te, div_rn_fast(F, Fp));
}

__global__ void sntemp_kernel(
    const float* __restrict__ T_a,
    const float* __restrict__ swrad,
    const float* __restrict__ e_a,
    const float* __restrict__ E,
    const float* __restrict__ elev,
    const float* __restrict__ T_g,
    const float* __restrict__ sfr,
    const float* __restrict__ albedo,
    const float* __restrict__ shade_total,
    const float* __restrict__ cloud_fraction,
    const float* __restrict__ T_0,
    float* __restrict__ out,
    int n)
{
    int i = blockIdx.x * blockDim.x + threadIdx.x;
    if (i >= n) return;

    const float A_CONST = 5.4e-8f;
    const float A4      = (float)(4.0 * 5.4e-8);
    const float EV_STB  = (float)(0.9 * 5.670373e-8);
    const float C2495E6 = (float)(2495.0 * 1e6);

    float ta  = T_a[i];
    float ea  = e_a[i];
    float st  = shade_total[i];
    float cf  = cloud_fraction[i];
    float Ein = E[i];

    // e_s = 6.108 * exp(17.26939*T_a / (237.3+T_a))
    float arg = __fdiv_rn(__fmul_rn(17.26939f, ta), __fadd_rn(237.3f, ta));
    float es  = __fmul_rn(6.108f, xla_vf32_exp(arg));

    // P = 1013.0 - 0.1055*elev   [plain]
    float P = __fsub_rn(1013.0f, __fmul_rn(0.1055f, elev[i]));

    // masked denominator (from pre-rounded es) [plain]
    float denom  = __fsub_rn(es, ea);
    float denom1 = __fmul_rn(denom, (denom >= 0.0f) ? 1.0f : 0.0f);
    float denom2 = __fadd_rn(denom1, (denom1 == 0.0f) ? 0.01f : 0.0f);
    float Bc = __fdiv_rn(__fmul_rn(0.00061f, P), denom2);

    // Tk4 = (ta+273.16)^4
    float tk  = __fadd_rn(ta, 273.16f);
    float tk2 = __fmul_rn(tk, tk);
    float Tk4 = __fmul_rn(tk2, tk2);

    // H_a  [plain]
    float h1 = __fadd_rn(3.354939e-8f, __fmul_rn(2.74995e-9f, __fsqrt_rn(ea)));
    float h2 = __fsub_rn(1.0f, st);
    float h3 = __fadd_rn(1.0f, __fmul_rn(0.17f, __fmul_rn(cf, cf)));
    float Ha = __fmul_rn(__fmul_rn(__fmul_rn(h1, h2), h3), Tk4);

    // H_s  [plain]
    float Hs = __fmul_rn(__fmul_rn(__fsub_rn(1.0f, albedo[i]), h2), swrad[i]);

    // H_v  [plain]
    float Hv = __fmul_rn(__fmul_rn(EV_STB, sfr[i]), Tk4);

    // B chain  [plain]
    float Em = __fmul_rn(1e6f, Ein);
    float b2 = __fadd_rn(2495.0f, __fmul_rn(2.36f, ta));
    float b4 = __fsub_rn(__fmul_rn(Bc, b2), 2.36f);
    float B  = __fadd_rn(__fmul_rn(Em, b4), 1.65f);

    // C  [plain]
    float C = __fmul_rn(__fmul_rn(Em, Bc), 2.36f);

    // D  [plain, reference association]
    float d3 = __fsub_rn(__fmul_rn(Bc, ta), 1.0f);
    float d4 = __fmul_rn(__fmul_rn(C2495E6, Ein), d3);
    float d5 = __fmul_rn(T_g[i], 1.65f);
    float D  = __fadd_rn(__fadd_rn(__fadd_rn(__fadd_rn(Ha, Hs), Hv), d4), d5);

    float C2 = __fmul_rn(2.0f, C);

    // Newton: 50 exact iterations as 25 FULLY-UNROLLED pairs, one combined
    // per-lane closure check per pair (R13 semantics, bit-exact).
    float Te = ta;
    #pragma unroll
    for (int j = 0; j < 25; ++j) {
        float T1 = newton_step(Te, B, C, C2, D);   // step 2j+1
        float T2 = newton_step(T1, B, C, C2, D);   // step 2j+2
        bool done = (T2 == T1) || (T2 == Te);
        Te = T2;
        if (done) break;
    }

    // Hi = F(T_0)  [plain — outside the loop]
    float t0   = T_0[i];
    float u    = __fadd_rn(t0, 273.16f);
    float u2   = __fmul_rn(u, u);
    float u4   = __fmul_rn(u2, u2);
    float t0sq = __fmul_rn(t0, t0);
    float Hi   = __fsub_rn(
                   __fadd_rn(
                     __fsub_rn(__fmul_rn(A_CONST, u4), __fmul_rn(C, t0sq)),
                     __fmul_rn(B, t0)),
                   D);

    // K1 = F'(Te)  [plain — outside the loop]
    float v  = __fadd_rn(Te, 273.16f);
    float v2 = __fmul_rn(v, v);
    float v3 = __fmul_rn(v2, v);
    float K1 = __fadd_rn(
                 __fsub_rn(__fmul_rn(A4, v3), __fmul_rn(C2, Te)),
                 B);

    // K2  [plain]
    float delt = __fsub_rn(t0, Te);
    float den  = __fmul_rn(delt, delt);
    float den1 = __fadd_rn(den, (den <= 1e-10f) ? 1.0f : 0.0f);
    float K2   = __fdiv_rn(__fsub_rn(__fmul_rn(K1, delt), Hi), den1);
    if (fabsf(delt) < 1e-10f) K2 = 0.0f;

    out[i]         = Te;
    out[n + i]     = K1;
    out[2 * n + i] = K2;
}

extern "C" void kernel_launch(void* const* d_in, const int* in_sizes, int n_in,
                              void* d_out, int out_size) {
    // metadata order: T_a, swrad, e_a, E, elev, slope, top_width, up_inflow,
    // T_g, shade_fraction_riparian, albedo, shade_total, cloud_fraction, T_0
    const float* T_a    = (const float*)d_in[0];
    const float* swrad  = (const float*)d_in[1];
    const float* e_a    = (const float*)d_in[2];
    const float* E      = (const float*)d_in[3];
    const float* elev   = (const float*)d_in[4];
    const float* T_g    = (const float*)d_in[8];
    const float* sfr    = (const float*)d_in[9];
    const float* albedo = (const float*)d_in[10];
    const float* stot   = (const float*)d_in[11];
    const float* cf     = (const float*)d_in[12];
    const float* T_0    = (const float*)d_in[13];

    int n = in_sizes[0];
    float* out = (float*)d_out;

    int threads = 256;
    int blocks  = (n + threads - 1) / threads;
    sntemp_kernel<<<blocks, threads>>>(T_a, swrad, e_a, E, elev, T_g, sfr,
                                       albedo, stot, cf, T_0, out, n);
}